// round 9
// baseline (speedup 1.0000x reference)
#include <cuda_runtime.h>
#include <cuda_bf16.h>

#define T_LEN 2048
#define VOCAB 1000

typedef unsigned long long ull;

// Gate table: tbl[tok*8 + g] = (i_g*0.5, f_g*0.5, g_g, o_g*0.5) as float4.
__device__ float4 d_tbl4[VOCAB * 8];

__global__ void build_table_kernel(const float* __restrict__ emb,
                                   const float* __restrict__ W_ih,
                                   const float* __restrict__ b_ih,
                                   const float* __restrict__ b_hh) {
    int tok = blockIdx.x;
    int j = threadIdx.x;  // gate index 0..31 (q*8+g)
    __shared__ float e[8];
    if (j < 8) e[j] = emb[tok * 8 + j];
    __syncthreads();
    float s = b_ih[j] + b_hh[j];
#pragma unroll
    for (int k = 0; k < 8; k++)
        s = fmaf(W_ih[j * 8 + k], e[k], s);
    int g = j & 7;
    int q = j >> 3;
    if (q != 2) s *= 0.5f;  // prescale sigmoid gates (i, f, o)
    reinterpret_cast<float*>(d_tbl4)[tok * 32 + g * 4 + q] = s;
}

__device__ __forceinline__ float tanha(float x) {
    float r;
    asm("tanh.approx.f32 %0, %1;" : "=f"(r) : "f"(x));
    return r;
}
__device__ __forceinline__ float sigm_pre(float a) {  // input prescaled by 0.5
    return fmaf(tanha(a), 0.5f, 0.5f);
}

// ---- f32x2 packed helpers ----
__device__ __forceinline__ ull packf2(float lo, float hi) {
    ull r;
    asm("mov.b64 %0, {%1, %2};" : "=l"(r) : "r"(__float_as_uint(lo)), "r"(__float_as_uint(hi)));
    return r;
}
__device__ __forceinline__ void unpackf2(ull p, float& lo, float& hi) {
    unsigned a, b;
    asm("mov.b64 {%0, %1}, %2;" : "=r"(a), "=r"(b) : "l"(p));
    lo = __uint_as_float(a);
    hi = __uint_as_float(b);
}
__device__ __forceinline__ void fma2(ull& d, ull a, ull b, ull c) {
    asm("fma.rn.f32x2 %0, %1, %2, %3;" : "=l"(d) : "l"(a), "l"(b), "l"(c));
}

// 256 threads/block, 128 blocks, 1 batch per 8 lanes (one chain per thread).
// h broadcast goes through shared memory (STS + syncwarp + 2x LDS.128),
// NOT shuffles — the R2/R3 data showed the SHFL traffic was the binder.
__global__ void __launch_bounds__(256)
lstm_scan_kernel(const int* __restrict__ x,
                 const float* __restrict__ W_hh,
                 const float* __restrict__ W_cls,
                 const float* __restrict__ b_cls,
                 float* __restrict__ out) {
    extern __shared__ float4 stbl[];  // VOCAB*8 float4 = 128000 B table
    float* hx = reinterpret_cast<float*>(stbl + VOCAB * 8);  // 2 x 256 floats

    for (int i = threadIdx.x; i < VOCAB * 8; i += blockDim.x)
        stbl[i] = d_tbl4[i];
    __syncthreads();

    int tid = blockIdx.x * blockDim.x + threadIdx.x;
    int b = tid >> 3;               // batch element
    int g = tid & 7;                // hidden unit owned by this lane
    int lt = threadIdx.x;           // thread within block
    int gbase = lt & ~7;            // base of this batch's 8-float h group

    // Weights packed by k-pairs: w2[q][kk] = (w_q[2kk], w_q[2kk+1]),
    // 0.5 prescale on sigmoid gates (q != 2). 16 ull = 32 regs.
    ull w2[4][4];
#pragma unroll
    for (int q = 0; q < 4; q++) {
        float sc = (q == 2) ? 1.0f : 0.5f;
#pragma unroll
        for (int kk = 0; kk < 4; kk++) {
            float wlo = sc * W_hh[(q * 8 + g) * 8 + 2 * kk];
            float whi = sc * W_hh[(q * 8 + g) * 8 + 2 * kk + 1];
            w2[q][kk] = packf2(wlo, whi);
        }
    }

    const int4* xr4 = reinterpret_cast<const int4*>(x + (size_t)b * T_LEN);

    float c = 0.0f, h = 0.0f;

    const int NCHUNK = T_LEN / 4;
    int4 cur = xr4[0];
    int4 nxt = xr4[1];
    float4 xg = stbl[(unsigned)cur.x * 8u + g];  // row for t=0

    for (int ch = 0; ch < NCHUNK; ch++) {
        int pf = ch + 2;
        if (pf >= NCHUNK) pf = NCHUNK - 1;
        int4 nxt2 = xr4[pf];

#pragma unroll
        for (int j = 0; j < 4; j++) {
            int ntok;
            if (j == 0)      ntok = cur.y;
            else if (j == 1) ntok = cur.z;
            else if (j == 2) ntok = cur.w;
            else             ntok = nxt.x;
            float4 xgn = stbl[(unsigned)ntok * 8u + g];  // 1-step table prefetch

            // ---- broadcast h within the 8-lane group via smem ----
            int slot = (j & 1) * 256;  // double buffer: one syncwarp per step
            hx[slot + lt] = h;
            __syncwarp(0xffffffffu);
            float4 hlo = *reinterpret_cast<const float4*>(&hx[slot + gbase]);
            float4 hhi = *reinterpret_cast<const float4*>(&hx[slot + gbase + 4]);
            ull h01 = packf2(hlo.x, hlo.y);
            ull h23 = packf2(hlo.z, hlo.w);
            ull h45 = packf2(hhi.x, hhi.y);
            ull h67 = packf2(hhi.z, hhi.w);

            // ---- gates: acc_q = (xg_q + sum_even, sum_odd), k-pair packed ----
            ull ai = packf2(xg.x, 0.f);
            ull af = packf2(xg.y, 0.f);
            ull ag = packf2(xg.z, 0.f);
            ull ao = packf2(xg.w, 0.f);
            fma2(ai, w2[0][0], h01, ai);
            fma2(af, w2[1][0], h01, af);
            fma2(ag, w2[2][0], h01, ag);
            fma2(ao, w2[3][0], h01, ao);
            fma2(ai, w2[0][1], h23, ai);
            fma2(af, w2[1][1], h23, af);
            fma2(ag, w2[2][1], h23, ag);
            fma2(ao, w2[3][1], h23, ao);
            fma2(ai, w2[0][2], h45, ai);
            fma2(af, w2[1][2], h45, af);
            fma2(ag, w2[2][2], h45, ag);
            fma2(ao, w2[3][2], h45, ao);
            fma2(ai, w2[0][3], h67, ai);
            fma2(af, w2[1][3], h67, af);
            fma2(ag, w2[2][3], h67, ag);
            fma2(ao, w2[3][3], h67, ao);

            float lo_, hi_;
            unpackf2(ai, lo_, hi_); float a_i = lo_ + hi_;
            unpackf2(af, lo_, hi_); float a_f = lo_ + hi_;
            unpackf2(ag, lo_, hi_); float a_g = lo_ + hi_;
            unpackf2(ao, lo_, hi_); float a_o = lo_ + hi_;

            float ig = sigm_pre(a_i);
            float fg = sigm_pre(a_f);
            float gg = tanha(a_g);
            float og = sigm_pre(a_o);
            c = fmaf(fg, c, ig * gg);
            h = og * tanha(c);

            xg = xgn;
        }
        cur = nxt;
        nxt = nxt2;
    }

    // classifier head
    float v = h * W_cls[g];
    v += __shfl_xor_sync(0xffffffffu, v, 4, 8);
    v += __shfl_xor_sync(0xffffffffu, v, 2, 8);
    v += __shfl_xor_sync(0xffffffffu, v, 1, 8);
    if (g == 0) {
        float z = v + b_cls[0];
        out[b] = 1.0f / (1.0f + __expf(-z));
    }
}

extern "C" void kernel_launch(void* const* d_in, const int* in_sizes, int n_in,
                              void* d_out, int out_size) {
    const int*   x     = (const int*)d_in[0];
    const float* emb   = (const float*)d_in[1];
    const float* W_ih  = (const float*)d_in[2];
    const float* W_hh  = (const float*)d_in[3];
    const float* b_ih  = (const float*)d_in[4];
    const float* b_hh  = (const float*)d_in[5];
    const float* W_cls = (const float*)d_in[6];
    const float* b_cls = (const float*)d_in[7];
    float* out = (float*)d_out;

    int B = in_sizes[0] / T_LEN;  // 4096

    build_table_kernel<<<VOCAB, 32>>>(emb, W_ih, b_ih, b_hh);

    size_t smem = (size_t)VOCAB * 8 * sizeof(float4) + 2 * 256 * sizeof(float);
    cudaFuncSetAttribute(lstm_scan_kernel,
                         cudaFuncAttributeMaxDynamicSharedMemorySize, (int)smem);

    int threads = B * 8;            // 32768
    int block = 256;
    int grid = threads / block;     // 128 blocks, 1 per SM, 2 warps/SMSP
    lstm_scan_kernel<<<grid, block, smem>>>(x, W_hh, W_cls, b_cls, out);
}

// round 10
// speedup vs baseline: 1.0005x; 1.0005x over previous
#include <cuda_runtime.h>
#include <cuda_bf16.h>

#define T_LEN 2048
#define VOCAB 1000

typedef unsigned long long ull;

// Gate table: tbl[tok*8 + g] = (i_g*0.5, f_g*0.5, g_g, o_g*0.5) as float4.
__device__ float4 d_tbl4[VOCAB * 8];

__global__ void build_table_kernel(const float* __restrict__ emb,
                                   const float* __restrict__ W_ih,
                                   const float* __restrict__ b_ih,
                                   const float* __restrict__ b_hh) {
    int tok = blockIdx.x;
    int j = threadIdx.x;  // gate index 0..31 (q*8+g)
    __shared__ float e[8];
    if (j < 8) e[j] = emb[tok * 8 + j];
    __syncthreads();
    float s = b_ih[j] + b_hh[j];
#pragma unroll
    for (int k = 0; k < 8; k++)
        s = fmaf(W_ih[j * 8 + k], e[k], s);
    int g = j & 7;
    int q = j >> 3;
    if (q != 2) s *= 0.5f;  // prescale sigmoid gates (i, f, o)
    reinterpret_cast<float*>(d_tbl4)[tok * 32 + g * 4 + q] = s;
}

__device__ __forceinline__ float tanha(float x) {
    float r;
    asm("tanh.approx.f32 %0, %1;" : "=f"(r) : "f"(x));
    return r;
}
__device__ __forceinline__ float sigm_pre(float a) {  // input prescaled by 0.5
    return fmaf(tanha(a), 0.5f, 0.5f);
}

// ---- f32x2 packed helpers ----
__device__ __forceinline__ ull packf2(float lo, float hi) {
    ull r;
    asm("mov.b64 %0, {%1, %2};" : "=l"(r) : "r"(__float_as_uint(lo)), "r"(__float_as_uint(hi)));
    return r;
}
__device__ __forceinline__ void unpackf2(ull p, float& lo, float& hi) {
    unsigned a, b;
    asm("mov.b64 {%0, %1}, %2;" : "=r"(a), "=r"(b) : "l"(p));
    lo = __uint_as_float(a);
    hi = __uint_as_float(b);
}
__device__ __forceinline__ void fma2(ull& d, ull a, ull b, ull c) {
    asm("fma.rn.f32x2 %0, %1, %2, %3;" : "=l"(d) : "l"(a), "l"(b), "l"(c));
}

// 256 threads/block, 128 blocks, 1 batch per 8 lanes (one chain per thread).
// h broadcast goes through shared memory (STS + syncwarp + 2x LDS.128),
// NOT shuffles — the R2/R3 data showed the SHFL traffic was the binder.
__global__ void __launch_bounds__(256)
lstm_scan_kernel(const int* __restrict__ x,
                 const float* __restrict__ W_hh,
                 const float* __restrict__ W_cls,
                 const float* __restrict__ b_cls,
                 float* __restrict__ out) {
    extern __shared__ float4 stbl[];  // VOCAB*8 float4 = 128000 B table
    float* hx = reinterpret_cast<float*>(stbl + VOCAB * 8);  // 2 x 256 floats

    for (int i = threadIdx.x; i < VOCAB * 8; i += blockDim.x)
        stbl[i] = d_tbl4[i];
    __syncthreads();

    int tid = blockIdx.x * blockDim.x + threadIdx.x;
    int b = tid >> 3;               // batch element
    int g = tid & 7;                // hidden unit owned by this lane
    int lt = threadIdx.x;           // thread within block
    int gbase = lt & ~7;            // base of this batch's 8-float h group

    // Weights packed by k-pairs: w2[q][kk] = (w_q[2kk], w_q[2kk+1]),
    // 0.5 prescale on sigmoid gates (q != 2). 16 ull = 32 regs.
    ull w2[4][4];
#pragma unroll
    for (int q = 0; q < 4; q++) {
        float sc = (q == 2) ? 1.0f : 0.5f;
#pragma unroll
        for (int kk = 0; kk < 4; kk++) {
            float wlo = sc * W_hh[(q * 8 + g) * 8 + 2 * kk];
            float whi = sc * W_hh[(q * 8 + g) * 8 + 2 * kk + 1];
            w2[q][kk] = packf2(wlo, whi);
        }
    }

    const int4* xr4 = reinterpret_cast<const int4*>(x + (size_t)b * T_LEN);

    float c = 0.0f, h = 0.0f;

    const int NCHUNK = T_LEN / 4;
    int4 cur = xr4[0];
    int4 nxt = xr4[1];
    float4 xg = stbl[(unsigned)cur.x * 8u + g];  // row for t=0

    for (int ch = 0; ch < NCHUNK; ch++) {
        int pf = ch + 2;
        if (pf >= NCHUNK) pf = NCHUNK - 1;
        int4 nxt2 = xr4[pf];

#pragma unroll
        for (int j = 0; j < 4; j++) {
            int ntok;
            if (j == 0)      ntok = cur.y;
            else if (j == 1) ntok = cur.z;
            else if (j == 2) ntok = cur.w;
            else             ntok = nxt.x;
            float4 xgn = stbl[(unsigned)ntok * 8u + g];  // 1-step table prefetch

            // ---- broadcast h within the 8-lane group via smem ----
            int slot = (j & 1) * 256;  // double buffer: one syncwarp per step
            hx[slot + lt] = h;
            __syncwarp(0xffffffffu);
            float4 hlo = *reinterpret_cast<const float4*>(&hx[slot + gbase]);
            float4 hhi = *reinterpret_cast<const float4*>(&hx[slot + gbase + 4]);
            ull h01 = packf2(hlo.x, hlo.y);
            ull h23 = packf2(hlo.z, hlo.w);
            ull h45 = packf2(hhi.x, hhi.y);
            ull h67 = packf2(hhi.z, hhi.w);

            // ---- gates: acc_q = (xg_q + sum_even, sum_odd), k-pair packed ----
            ull ai = packf2(xg.x, 0.f);
            ull af = packf2(xg.y, 0.f);
            ull ag = packf2(xg.z, 0.f);
            ull ao = packf2(xg.w, 0.f);
            fma2(ai, w2[0][0], h01, ai);
            fma2(af, w2[1][0], h01, af);
            fma2(ag, w2[2][0], h01, ag);
            fma2(ao, w2[3][0], h01, ao);
            fma2(ai, w2[0][1], h23, ai);
            fma2(af, w2[1][1], h23, af);
            fma2(ag, w2[2][1], h23, ag);
            fma2(ao, w2[3][1], h23, ao);
            fma2(ai, w2[0][2], h45, ai);
            fma2(af, w2[1][2], h45, af);
            fma2(ag, w2[2][2], h45, ag);
            fma2(ao, w2[3][2], h45, ao);
            fma2(ai, w2[0][3], h67, ai);
            fma2(af, w2[1][3], h67, af);
            fma2(ag, w2[2][3], h67, ag);
            fma2(ao, w2[3][3], h67, ao);

            float lo_, hi_;
            unpackf2(ai, lo_, hi_); float a_i = lo_ + hi_;
            unpackf2(af, lo_, hi_); float a_f = lo_ + hi_;
            unpackf2(ag, lo_, hi_); float a_g = lo_ + hi_;
            unpackf2(ao, lo_, hi_); float a_o = lo_ + hi_;

            float ig = sigm_pre(a_i);
            float fg = sigm_pre(a_f);
            float gg = tanha(a_g);
            float og = sigm_pre(a_o);
            c = fmaf(fg, c, ig * gg);
            h = og * tanha(c);

            xg = xgn;
        }
        cur = nxt;
        nxt = nxt2;
    }

    // classifier head
    float v = h * W_cls[g];
    v += __shfl_xor_sync(0xffffffffu, v, 4, 8);
    v += __shfl_xor_sync(0xffffffffu, v, 2, 8);
    v += __shfl_xor_sync(0xffffffffu, v, 1, 8);
    if (g == 0) {
        float z = v + b_cls[0];
        out[b] = 1.0f / (1.0f + __expf(-z));
    }
}

extern "C" void kernel_launch(void* const* d_in, const int* in_sizes, int n_in,
                              void* d_out, int out_size) {
    const int*   x     = (const int*)d_in[0];
    const float* emb   = (const float*)d_in[1];
    const float* W_ih  = (const float*)d_in[2];
    const float* W_hh  = (const float*)d_in[3];
    const float* b_ih  = (const float*)d_in[4];
    const float* b_hh  = (const float*)d_in[5];
    const float* W_cls = (const float*)d_in[6];
    const float* b_cls = (const float*)d_in[7];
    float* out = (float*)d_out;

    int B = in_sizes[0] / T_LEN;  // 4096

    build_table_kernel<<<VOCAB, 32>>>(emb, W_ih, b_ih, b_hh);

    size_t smem = (size_t)VOCAB * 8 * sizeof(float4) + 2 * 256 * sizeof(float);
    cudaFuncSetAttribute(lstm_scan_kernel,
                         cudaFuncAttributeMaxDynamicSharedMemorySize, (int)smem);

    int threads = B * 8;            // 32768
    int block = 256;
    int grid = threads / block;     // 128 blocks, 1 per SM, 2 warps/SMSP
    lstm_scan_kernel<<<grid, block, smem>>>(x, W_hh, W_cls, b_cls, out);
}